// round 11
// baseline (speedup 1.0000x reference)
#include <cuda_runtime.h>
#include <cstdint>

// Problem constants (match reference)
#define BB 32
#define QQ 512
#define RR 1024
#define LL 1536
#define DD 2048
#define MAXRL 1024
#define GAMMA_F 0.99f
#define LMBDA_F 0.95f

#define NVB (BB*RR/8)          // 4096 value blocks

// ---------------- output layout (flattened tuple, float32) ----------------
#define OFF_VAL 0
#define OFF_VPM (BB*RR)
#define OFF_VLP (2*BB*RR)
#define OFF_SC  (2*BB*RR + BB)
#define OFF_RLP (2*BB*RR + 2*BB)
#define OFF_KL  (2*BB*RR + 3*BB)
#define OFF_KLR (3*BB*RR + 3*BB)
#define OFF_ADV (4*BB*RR + 3*BB)
#define OFF_RET (5*BB*RR + 3*BB)

// ---------------- device scratch (no allocations allowed) ----------------
// All counters are MONOTONIC (zero at module load, only incremented) so the
// kernel is graph-replay deterministic with no reset pass:
//   per launch: g_done += 4096, g_arrive += 32, g_stats += 32.
__device__ unsigned g_done;
__device__ unsigned g_arrive;
__device__ unsigned g_stats;
__device__ double   g_psum[BB];
__device__ double   g_psq[BB];
__device__ double   g_pcnt[BB];

// ========================================================================
// ONE kernel, block-specialized producer/consumer.
//  blocks 0..4095   : values_raw = hidden[:, Q-1:L-1].(wb+wa), warp-per-row
//                     (8 rows/block, float4). Signal g_done when finished.
//  blocks 4096..4127: per-batch meta + score + kl/klr (all independent of
//                     values), then spin until all value blocks of THIS
//                     launch are done, then GAE + whitening in-place.
// ========================================================================
__global__ void __launch_bounds__(256) k_fused(
    const float* __restrict__ hidden, const float* __restrict__ wb,
    const float* __restrict__ wa, const int* __restrict__ pad,
    const float* __restrict__ gen, const float* __restrict__ ref,
    float* __restrict__ out)
{
    int tid = threadIdx.x;
    int lane = tid & 31, warp = tid >> 5;

    if (blockIdx.x < NVB) {
        // ================= values path (DRAM roofline) =================
        __shared__ float ws[DD];
        #pragma unroll
        for (int i = tid; i < DD; i += 256) ws[i] = wb[i] + wa[i];
        __syncthreads();

        int row = blockIdx.x * 8 + warp;          // 0 .. 32767
        int b = row >> 10, t = row & 1023;
        const float4* h  = (const float4*)(hidden + ((size_t)b * LL + (QQ - 1) + t) * DD);
        const float4* w4 = (const float4*)ws;

        float acc = 0.f;
        #pragma unroll
        for (int k = 0; k < 16; k++) {
            int i4 = lane + k * 32;
            float4 v = h[i4];
            float4 w = w4[i4];
            acc += v.x * w.x + v.y * w.y + v.z * w.z + v.w * w.w;
        }
        #pragma unroll
        for (int o = 16; o; o >>= 1) acc += __shfl_down_sync(0xffffffffu, acc, o);
        if (lane == 0) out[OFF_VAL + row] = acc;   // raw, unmasked

        // signal: my 8 raw values are globally visible
        __threadfence();
        __syncthreads();
        if (tid == 0) atomicAdd(&g_done, 1u);
        return;
    }

    // ================= meta + score + kl + GAE + whiten =================
    __shared__ int s_last[8], s_any[8];
    __shared__ int sh_pos, sh_pen, sh_vlp;
    __shared__ float red[8];
    __shared__ float sh_score;
    __shared__ float svm[32 * 33];    // vm: element t at (t>>5)*33 + (t&31)
    __shared__ float su [32 * 33];    // u-partials, then reused for adv
    __shared__ double s_red[3][8];
    __shared__ double sh_mean, sh_inv;

    const float c = GAMMA_F * LMBDA_F;     // 0.9405
    int b = blockIdx.x - NVB;
    int base = b * RR;

    // ---- meta: rlp / vlp / penalty from int32-marshalled bool mask ----
    const int* p = pad + (size_t)b * RR;
    int last = -1, anyp = 0;
    #pragma unroll
    for (int i = tid; i < RR; i += 256) {
        int v = p[i];
        anyp |= v;
        if (!v) last = i;          // i strictly increasing -> max survives
    }
    #pragma unroll
    for (int o = 16; o; o >>= 1) {
        last = max(last, __shfl_down_sync(0xffffffffu, last, o));
        anyp |= __shfl_down_sync(0xffffffffu, anyp, o);
    }
    if (lane == 0) { s_last[warp] = last; s_any[warp] = anyp; }
    __syncthreads();
    if (tid == 0) {
        int L = -1, A = 0;
        #pragma unroll
        for (int i = 0; i < 8; i++) { L = max(L, s_last[i]); A |= s_any[i]; }
        int rlp = L < 0 ? 0 : L;
        int vlp = (rlp > 0 && rlp < MAXRL - 1) ? rlp + 1 : rlp;
        sh_vlp = vlp;
        sh_pos = QQ + rlp;
        sh_pen = !A;                       // PENALISE_NO_EOS
        out[OFF_VLP + b] = (float)vlp;
        out[OFF_RLP + b] = (float)rlp;
    }
    __syncthreads();

    // ---- score dot at gathered row ----
    {
        const float4* h  = (const float4*)(hidden + ((size_t)b * LL + sh_pos) * DD);
        const float4* w4 = (const float4*)wb;
        float acc = 0.f;
        #pragma unroll
        for (int i = tid; i < DD / 4; i += 256) {
            float4 v = h[i]; float4 w = w4[i];
            acc += v.x * w.x + v.y * w.y + v.z * w.z + v.w * w.w;
        }
        #pragma unroll
        for (int o = 16; o; o >>= 1) acc += __shfl_down_sync(0xffffffffu, acc, o);
        if (lane == 0) red[warp] = acc;
        __syncthreads();
        if (tid == 0) {
            float s = 0.f;
            #pragma unroll
            for (int i = 0; i < 8; i++) s += red[i];
            if (sh_pen) s = -3.0f;         // REWARD_PENALTY
            sh_score = s;
            out[OFF_SC + b] = s;
        }
    }

    // ---- kl / kl_rewards (independent of values; overlaps producers) ----
    float klrk[4];
    int   pdk[4];
    #pragma unroll
    for (int k = 0; k < 4; k++) {
        int t = k * 256 + tid;
        int idx = base + t;
        float kl  = gen[idx] - ref[idx];
        float klr = -0.1f * kl;            // KL_COEFF
        klrk[k] = klr;
        pdk[k]  = pad[idx];
        out[OFF_KL  + idx] = kl;
        out[OFF_KLR + idx] = klr;
    }
    __syncthreads();
    int vlp = sh_vlp;
    float score = sh_score;

    // ---- wait for all 4096 value blocks of THIS launch ----
    if (tid == 0) {
        unsigned my = atomicAdd(&g_arrive, 1u);
        unsigned target = ((my >> 5) + 1u) * (unsigned)NVB;   // epoch-aligned
        while (*(volatile unsigned*)&g_done < target) __nanosleep(128);
    }
    __syncthreads();
    __threadfence();                        // acquire raw values

    // ---- pass 1: mask fixup, emit values/vpm, stage vm & u ----
    float vmk[4];
    #pragma unroll
    for (int k = 0; k < 4; k++) {
        int t = k * 256 + tid;
        int idx = base + t;
        float raw = out[OFF_VAL + idx];     // L2-hot
        int vpm = (pdk[k] != 0) && (t != vlp);
        float vm = vpm ? 0.f : raw;
        vmk[k] = vm;
        out[OFF_VAL + idx] = vm;
        out[OFF_VPM + idx] = vpm ? 1.f : 0.f;
        float r = klrk[k] + ((t == vlp) ? score : 0.f);
        int pp = (t >> 5) * 33 + (t & 31);
        svm[pp] = vm;
        su [pp] = r - vm;                   // gamma*v_next added in pass 2
    }
    __syncthreads();

    // ---- pass 2: suffix scan on warp 0 ----
    if (warp == 0) {
        float u[32];
        #pragma unroll
        for (int j = 0; j < 32; j++) {
            int pp = lane * 33 + j;
            float vnext = (j < 31) ? svm[pp + 1]
                        : (lane < 31 ? svm[(lane + 1) * 33] : 0.f);  // v[1024]=0
            u[j] = su[pp] + GAMMA_F * vnext;
        }
        #pragma unroll
        for (int j = 30; j >= 0; j--) u[j] += c * u[j + 1];   // intra-lane scan

        float x = u[0];
        float W = c;
        W = W * W; W = W * W; W = W * W; W = W * W; W = W * W;   // c^32
        #pragma unroll
        for (int o = 1; o < 32; o <<= 1) {
            float oth = __shfl_down_sync(0xffffffffu, x, o);
            x += W * ((lane + o < 32) ? oth : 0.f);
            W *= W;
        }
        float carry = __shfl_down_sync(0xffffffffu, x, 1);
        if (lane == 31) carry = 0.f;

        float pw = c;
        #pragma unroll
        for (int j = 31; j >= 0; j--) {
            su[lane * 33 + j] = u[j] + pw * carry;   // adv
            pw *= c;
        }
    }
    __syncthreads();

    // ---- pass 3: returns + masked double partials ----
    double da = 0.0, dq = 0.0, dn = 0.0;
    float advk[4];
    #pragma unroll
    for (int k = 0; k < 4; k++) {
        int t = k * 256 + tid;
        int idx = base + t;
        float adv = su[(t >> 5) * 33 + (t & 31)];
        advk[k] = adv;
        out[OFF_RET + idx] = adv + vmk[k];
        if (pdk[k] == 0) {
            da += (double)adv;
            dq += (double)adv * (double)adv;
            dn += 1.0;
        }
    }
    #pragma unroll
    for (int o = 16; o; o >>= 1) {
        da += __shfl_down_sync(0xffffffffu, da, o);
        dq += __shfl_down_sync(0xffffffffu, dq, o);
        dn += __shfl_down_sync(0xffffffffu, dn, o);
    }
    if (lane == 0) { s_red[0][warp] = da; s_red[1][warp] = dq; s_red[2][warp] = dn; }
    __syncthreads();
    if (tid == 0) {
        double S = 0, Q2 = 0, N = 0;
        #pragma unroll
        for (int i = 0; i < 8; i++) { S += s_red[0][i]; Q2 += s_red[1][i]; N += s_red[2][i]; }
        g_psum[b] = S; g_psq[b] = Q2; g_pcnt[b] = N;
    }

    // ---- stats barrier among the 32 GAE blocks (monotonic epoch) ----
    __threadfence();                        // partials visible
    __syncthreads();
    if (tid == 0) {
        unsigned my = atomicAdd(&g_stats, 1u);
        unsigned target = ((my >> 5) + 1u) << 5;      // next multiple of 32
        while (*(volatile unsigned*)&g_stats < target) __nanosleep(64);
    }
    __syncthreads();
    __threadfence();                        // acquire partials

    // ---- pass 4: redundant stats (warp 0) + whiten ----
    if (tid < 32) {
        double ra = *(volatile double*)&g_psum[tid];
        double rq = *(volatile double*)&g_psq [tid];
        double rn = *(volatile double*)&g_pcnt[tid];
        #pragma unroll
        for (int o = 16; o; o >>= 1) {
            ra += __shfl_down_sync(0xffffffffu, ra, o);
            rq += __shfl_down_sync(0xffffffffu, rq, o);
            rn += __shfl_down_sync(0xffffffffu, rn, o);
        }
        if (tid == 0) {
            double mean = ra / rn;
            double var  = (rq / rn - mean * mean) * (rn / (rn - 1.0));
            sh_mean = mean;
            sh_inv  = 1.0 / sqrt(var + 1e-8);
        }
    }
    __syncthreads();
    double mean = sh_mean, inv = sh_inv;
    #pragma unroll
    for (int k = 0; k < 4; k++) {
        int idx = base + k * 256 + tid;
        float w = (float)(((double)advk[k] - mean) * inv);
        out[OFF_ADV + idx] = (pdk[k] == 0) ? w : 0.f;
    }
}

// ========================================================================
extern "C" void kernel_launch(void* const* d_in, const int* in_sizes, int n_in,
                              void* d_out, int out_size) {
    const float* hidden = (const float*)d_in[0];
    const float* wb     = (const float*)d_in[1];
    const float* wa     = (const float*)d_in[2];
    const float* gen    = (const float*)d_in[3];
    const float* ref    = (const float*)d_in[4];
    const int*   pad    = (const int*)d_in[5];   // JAX bool -> int32 marshalling
    float* out = (float*)d_out;

    k_fused<<<NVB + BB, 256>>>(hidden, wb, wa, pad, gen, ref, out);
}

// round 13
// speedup vs baseline: 1.1548x; 1.1548x over previous
#include <cuda_runtime.h>
#include <cstdint>

// Problem constants (match reference)
#define BB 32
#define QQ 512
#define RR 1024
#define LL 1536
#define DD 2048
#define MAXRL 1024
#define GAMMA_F 0.99f
#define LMBDA_F 0.95f

#define NVB (BB*RR/8)          // 4096 value blocks

// ---------------- output layout (flattened tuple, float32) ----------------
#define OFF_VAL 0
#define OFF_VPM (BB*RR)
#define OFF_VLP (2*BB*RR)
#define OFF_SC  (2*BB*RR + BB)
#define OFF_RLP (2*BB*RR + 2*BB)
#define OFF_KL  (2*BB*RR + 3*BB)
#define OFF_KLR (3*BB*RR + 3*BB)
#define OFF_ADV (4*BB*RR + 3*BB)
#define OFF_RET (5*BB*RR + 3*BB)

// ---------------- device scratch (no allocations allowed) ----------------
__device__ int      g_vlp[BB];
__device__ float    g_score[BB];
__device__ double   g_psum[BB];
__device__ double   g_psq[BB];
__device__ double   g_pcnt[BB];
__device__ unsigned g_stats;   // monotonic epoch counter (+8 per launch,
                               // zero at module load, replay-safe, no reset)

// ========================================================================
// K_A: block-specialized, LEAN footprint (no GAE state in this kernel).
//  blocks 0..4095  : one batch each (8 rows). Redundantly derive this
//                    batch's vlp from a 4KB L2-hot mask scan, then
//                    warp-per-row float4 dots and write FINAL masked
//                    values + vpm. DRAM-roofline path.
//  blocks 4096..4127: per-batch meta (rlp/vlp/score/penalty -> globals +
//                    out) AND kl/kl_rewards for that batch.
// ========================================================================
__global__ void __launch_bounds__(256) k_main(
    const float* __restrict__ hidden, const float* __restrict__ wb,
    const float* __restrict__ wa, const int* __restrict__ pad,
    const float* __restrict__ gen, const float* __restrict__ ref,
    float* __restrict__ out)
{
    int tid = threadIdx.x;
    int lane = tid & 31, warp = tid >> 5;

    if (blockIdx.x < NVB) {
        // ================= values path =================
        __shared__ float ws[DD];
        __shared__ int s_last[8];
        __shared__ int sh_vlp;

        #pragma unroll
        for (int i = tid; i < DD; i += 256) ws[i] = wb[i] + wa[i];

        // redundant per-block vlp from this batch's mask (L2-hot, 4KB)
        int b = blockIdx.x >> 7;               // 128 blocks per batch
        const int* p = pad + (size_t)b * RR;
        int last = -1;
        #pragma unroll
        for (int k = 0; k < 4; k++) {
            int i = k * 256 + tid;
            if (!p[i]) last = i;               // i increasing -> max survives
        }
        #pragma unroll
        for (int o = 16; o; o >>= 1)
            last = max(last, __shfl_down_sync(0xffffffffu, last, o));
        if (lane == 0) s_last[warp] = last;
        __syncthreads();
        if (tid == 0) {
            int L = -1;
            #pragma unroll
            for (int i = 0; i < 8; i++) L = max(L, s_last[i]);
            int rlp = L < 0 ? 0 : L;
            sh_vlp = (rlp > 0 && rlp < MAXRL - 1) ? rlp + 1 : rlp;
        }
        __syncthreads();

        int row = blockIdx.x * 8 + warp;       // 0 .. 32767 (same batch b)
        int t = row & 1023;
        const float4* h  = (const float4*)(hidden + ((size_t)b * LL + (QQ - 1) + t) * DD);
        const float4* w4 = (const float4*)ws;

        float acc = 0.f;
        #pragma unroll
        for (int k = 0; k < 16; k++) {
            int i4 = lane + k * 32;
            float4 v = h[i4];
            float4 w = w4[i4];
            acc += v.x * w.x + v.y * w.y + v.z * w.z + v.w * w.w;
        }
        #pragma unroll
        for (int o = 16; o; o >>= 1) acc += __shfl_down_sync(0xffffffffu, acc, o);

        if (lane == 0) {
            int vpm = (p[t] != 0) && (t != sh_vlp);
            out[OFF_VAL + row] = vpm ? 0.f : acc;     // FINAL masked value
            out[OFF_VPM + row] = vpm ? 1.f : 0.f;
        }
    } else {
        // ================= meta + score + kl path =================
        __shared__ int s_last[8], s_any[8];
        __shared__ int sh_pos;
        __shared__ float red[8];

        int b = blockIdx.x - NVB;
        const int* p = pad + (size_t)b * RR;
        int last = -1, anyp = 0;
        #pragma unroll
        for (int k = 0; k < 4; k++) {
            int i = k * 256 + tid;
            int v = p[i];
            anyp |= v;
            if (!v) last = i;
        }
        #pragma unroll
        for (int o = 16; o; o >>= 1) {
            last = max(last, __shfl_down_sync(0xffffffffu, last, o));
            anyp |= __shfl_down_sync(0xffffffffu, anyp, o);
        }
        if (lane == 0) { s_last[warp] = last; s_any[warp] = anyp; }
        __syncthreads();
        if (tid == 0) {
            int L = -1, A = 0;
            #pragma unroll
            for (int i = 0; i < 8; i++) { L = max(L, s_last[i]); A |= s_any[i]; }
            int rlp = L < 0 ? 0 : L;
            int vlp = (rlp > 0 && rlp < MAXRL - 1) ? rlp + 1 : rlp;
            g_vlp[b] = vlp;
            sh_pos = QQ + rlp;
            s_any[0] = !A;                     // penalty flag (reuse smem)
            out[OFF_VLP + b] = (float)vlp;
            out[OFF_RLP + b] = (float)rlp;
        }
        __syncthreads();
        int pen = s_any[0];

        // score dot at gathered row
        const float4* h  = (const float4*)(hidden + ((size_t)b * LL + sh_pos) * DD);
        const float4* w4 = (const float4*)wb;
        float acc = 0.f;
        #pragma unroll
        for (int i = tid; i < DD / 4; i += 256) {
            float4 v = h[i]; float4 w = w4[i];
            acc += v.x * w.x + v.y * w.y + v.z * w.z + v.w * w.w;
        }
        #pragma unroll
        for (int o = 16; o; o >>= 1) acc += __shfl_down_sync(0xffffffffu, acc, o);
        if (lane == 0) red[warp] = acc;
        __syncthreads();
        if (tid == 0) {
            float s = 0.f;
            #pragma unroll
            for (int i = 0; i < 8; i++) s += red[i];
            if (pen) s = -3.0f;                // REWARD_PENALTY
            g_score[b] = s;
            out[OFF_SC + b] = s;
        }

        // kl / kl_rewards (overlaps the DRAM stream of value blocks)
        int base = b * RR;
        #pragma unroll
        for (int k = 0; k < 4; k++) {
            int idx = base + k * 256 + tid;
            float kl  = gen[idx] - ref[idx];
            out[OFF_KL  + idx] = kl;
            out[OFF_KLR + idx] = -0.1f * kl;   // KL_COEFF
        }
    }
}

// ========================================================================
// K_B: GAE + whitening. 8 blocks x 128 threads, WARP-PER-BATCH (4 batches
// per block). Per-warp 33-stride SMEM transpose (34KB static/block). All
// inputs L2-hot (written by K_A). Only an 8-arrival grid barrier for the
// whitening stats (monotonic epoch counter, replay-safe).
// ========================================================================
__global__ void __launch_bounds__(128) k_gae_whiten(
    const int* __restrict__ pad, float* __restrict__ out)
{
    __shared__ float svm[4 * 1056];   // per-warp 32*33 region: vm
    __shared__ float su [4 * 1056];   // per-warp: u-partials, then adv

    const float c = GAMMA_F * LMBDA_F;     // 0.9405
    int lane = threadIdx.x & 31, warp = threadIdx.x >> 5;
    int b = blockIdx.x * 4 + warp;
    int base = b * RR;
    int vlp = g_vlp[b];
    float score = g_score[b];
    float* mvm = svm + warp * 1056;
    float* mu  = su  + warp * 1056;

    // ---- pass 1: coalesced loads (all L2-hot), stage vm & u-partials ----
    unsigned pdmask = 0;                   // bit k set => pad at t=k*32+lane
    #pragma unroll
    for (int k = 0; k < 32; k++) {
        int t = k * 32 + lane;
        int idx = base + t;
        float vm  = out[OFF_VAL + idx];    // final masked value from K_A
        float klr = out[OFF_KLR + idx];
        if (pad[idx]) pdmask |= 1u << k;
        float r = klr + ((t == vlp) ? score : 0.f);
        mvm[k * 33 + lane] = vm;
        mu [k * 33 + lane] = r - vm;       // gamma*v_next added in pass 2
    }
    __syncwarp();

    // ---- pass 2: chunked scan (lane owns t = lane*32 .. lane*32+31) ----
    float u[32];
    #pragma unroll
    for (int j = 0; j < 32; j++) {
        int pp = lane * 33 + j;
        float vnext = (j < 31) ? mvm[pp + 1]
                    : (lane < 31 ? mvm[(lane + 1) * 33] : 0.f);  // v[1024]=0
        u[j] = mu[pp] + GAMMA_F * vnext;
    }
    #pragma unroll
    for (int j = 30; j >= 0; j--) u[j] += c * u[j + 1];   // intra-lane scan

    float x = u[0];
    float W = c;
    W = W * W; W = W * W; W = W * W; W = W * W; W = W * W;   // c^32
    #pragma unroll
    for (int o = 1; o < 32; o <<= 1) {
        float oth = __shfl_down_sync(0xffffffffu, x, o);
        x += W * ((lane + o < 32) ? oth : 0.f);
        W *= W;
    }
    float carry = __shfl_down_sync(0xffffffffu, x, 1);  // adv of next chunk head
    if (lane == 31) carry = 0.f;

    __syncwarp();
    float pw = c;
    #pragma unroll
    for (int j = 31; j >= 0; j--) {
        mu[lane * 33 + j] = u[j] + pw * carry;   // adv
        pw *= c;
    }
    __syncwarp();

    // ---- pass 3: returns + per-batch masked double partials ----
    double da = 0.0, dq = 0.0, dn = 0.0;
    #pragma unroll
    for (int k = 0; k < 32; k++) {
        int idx = base + k * 32 + lane;
        float adv = mu [k * 33 + lane];
        float vm  = mvm[k * 33 + lane];
        out[OFF_RET + idx] = adv + vm;
        if (!((pdmask >> k) & 1u)) {
            da += (double)adv;
            dq += (double)adv * (double)adv;
            dn += 1.0;
        }
    }
    #pragma unroll
    for (int o = 16; o; o >>= 1) {
        da += __shfl_down_sync(0xffffffffu, da, o);
        dq += __shfl_down_sync(0xffffffffu, dq, o);
        dn += __shfl_down_sync(0xffffffffu, dn, o);
    }
    if (lane == 0) { g_psum[b] = da; g_psq[b] = dq; g_pcnt[b] = dn; }

    // ---- 8-arrival grid barrier (monotonic epoch, replay-safe) ----
    __threadfence();                       // partials visible
    __syncthreads();
    if (threadIdx.x == 0) {
        unsigned my = atomicAdd(&g_stats, 1u);
        unsigned target = ((my >> 3) + 1u) << 3;     // next multiple of 8
        while (*(volatile unsigned*)&g_stats < target) __nanosleep(64);
    }
    __syncthreads();
    __threadfence();                       // acquire partials

    // ---- pass 4: redundant stats (per warp) + whiten ----
    double ra = *(volatile double*)&g_psum[lane];
    double rq = *(volatile double*)&g_psq [lane];
    double rn = *(volatile double*)&g_pcnt[lane];
    #pragma unroll
    for (int o = 16; o; o >>= 1) {
        ra += __shfl_down_sync(0xffffffffu, ra, o);
        rq += __shfl_down_sync(0xffffffffu, rq, o);
        rn += __shfl_down_sync(0xffffffffu, rn, o);
    }
    double mean, inv;
    if (lane == 0) {
        mean = ra / rn;
        double var = (rq / rn - mean * mean) * (rn / (rn - 1.0));
        inv = 1.0 / sqrt(var + 1e-8);
    }
    mean = __shfl_sync(0xffffffffu, mean, 0);
    inv  = __shfl_sync(0xffffffffu, inv, 0);

    #pragma unroll
    for (int k = 0; k < 32; k++) {
        int idx = base + k * 32 + lane;
        float adv = mu[k * 33 + lane];
        float w = (float)(((double)adv - mean) * inv);
        out[OFF_ADV + idx] = ((pdmask >> k) & 1u) ? 0.f : w;
    }
}

// ========================================================================
extern "C" void kernel_launch(void* const* d_in, const int* in_sizes, int n_in,
                              void* d_out, int out_size) {
    const float* hidden = (const float*)d_in[0];
    const float* wb     = (const float*)d_in[1];
    const float* wa     = (const float*)d_in[2];
    const float* gen    = (const float*)d_in[3];
    const float* ref    = (const float*)d_in[4];
    const int*   pad    = (const int*)d_in[5];   // JAX bool -> int32 marshalling
    float* out = (float*)d_out;

    k_main      <<<NVB + BB, 256>>>(hidden, wb, wa, pad, gen, ref, out);
    k_gae_whiten<<<8,        128>>>(pad, out);
}

// round 16
// speedup vs baseline: 1.2221x; 1.0582x over previous
#include <cuda_runtime.h>
#include <cstdint>

// Problem constants (match reference)
#define BB 32
#define QQ 512
#define RR 1024
#define LL 1536
#define DD 2048
#define MAXRL 1024
#define GAMMA_F 0.99f
#define LMBDA_F 0.95f

#define NVB (BB*RR/8)          // 4096 value blocks

// ---------------- output layout (flattened tuple, float32) ----------------
#define OFF_VAL 0
#define OFF_VPM (BB*RR)
#define OFF_VLP (2*BB*RR)
#define OFF_SC  (2*BB*RR + BB)
#define OFF_RLP (2*BB*RR + 2*BB)
#define OFF_KL  (2*BB*RR + 3*BB)
#define OFF_KLR (3*BB*RR + 3*BB)
#define OFF_ADV (4*BB*RR + 3*BB)
#define OFF_RET (5*BB*RR + 3*BB)

// ---------------- device scratch (no allocations allowed) ----------------
__device__ int      g_vlp[BB];
__device__ float    g_score[BB];
__device__ double   g_psum[BB];
__device__ double   g_psq[BB];
__device__ double   g_pcnt[BB];
__device__ unsigned g_stats;   // monotonic epoch counter (+32 per launch,
                               // zero at module load, replay-safe, no reset)

// ========================================================================
// K_A: block-specialized, LEAN footprint.
//  blocks 0..4095  : one batch each (8 rows). Redundantly derive this
//                    batch's vlp from a 4KB L2-hot mask scan, then
//                    warp-per-row float4 dots and write FINAL masked
//                    values + vpm. DRAM-roofline path.
//  blocks 4096..4127: per-batch meta (rlp/vlp/score/penalty) + kl/klr
//                    (overlaps the DRAM stream of the value blocks).
// ========================================================================
__global__ void __launch_bounds__(256) k_main(
    const float* __restrict__ hidden, const float* __restrict__ wb,
    const float* __restrict__ wa, const int* __restrict__ pad,
    const float* __restrict__ gen, const float* __restrict__ ref,
    float* __restrict__ out)
{
    int tid = threadIdx.x;
    int lane = tid & 31, warp = tid >> 5;

    if (blockIdx.x < NVB) {
        // ================= values path =================
        __shared__ float ws[DD];
        __shared__ int s_last[8];
        __shared__ int sh_vlp;

        #pragma unroll
        for (int i = tid; i < DD; i += 256) ws[i] = wb[i] + wa[i];

        // redundant per-block vlp from this batch's mask (L2-hot, 4KB)
        int b = blockIdx.x >> 7;               // 128 blocks per batch
        const int* p = pad + (size_t)b * RR;
        int last = -1;
        #pragma unroll
        for (int k = 0; k < 4; k++) {
            int i = k * 256 + tid;
            if (!p[i]) last = i;               // i increasing -> max survives
        }
        #pragma unroll
        for (int o = 16; o; o >>= 1)
            last = max(last, __shfl_down_sync(0xffffffffu, last, o));
        if (lane == 0) s_last[warp] = last;
        __syncthreads();
        if (tid == 0) {
            int L = -1;
            #pragma unroll
            for (int i = 0; i < 8; i++) L = max(L, s_last[i]);
            int rlp = L < 0 ? 0 : L;
            sh_vlp = (rlp > 0 && rlp < MAXRL - 1) ? rlp + 1 : rlp;
        }
        __syncthreads();

        int row = blockIdx.x * 8 + warp;       // 0 .. 32767 (same batch b)
        int t = row & 1023;
        const float4* h  = (const float4*)(hidden + ((size_t)b * LL + (QQ - 1) + t) * DD);
        const float4* w4 = (const float4*)ws;

        float acc = 0.f;
        #pragma unroll
        for (int k = 0; k < 16; k++) {
            int i4 = lane + k * 32;
            float4 v = h[i4];
            float4 w = w4[i4];
            acc += v.x * w.x + v.y * w.y + v.z * w.z + v.w * w.w;
        }
        #pragma unroll
        for (int o = 16; o; o >>= 1) acc += __shfl_down_sync(0xffffffffu, acc, o);

        if (lane == 0) {
            int vpm = (p[t] != 0) && (t != sh_vlp);
            out[OFF_VAL + row] = vpm ? 0.f : acc;     // FINAL masked value
            out[OFF_VPM + row] = vpm ? 1.f : 0.f;
        }
    } else {
        // ================= meta + score + kl path =================
        __shared__ int s_last[8], s_any[8];
        __shared__ int sh_pos;
        __shared__ float red[8];

        int b = blockIdx.x - NVB;
        const int* p = pad + (size_t)b * RR;
        int last = -1, anyp = 0;
        #pragma unroll
        for (int k = 0; k < 4; k++) {
            int i = k * 256 + tid;
            int v = p[i];
            anyp |= v;
            if (!v) last = i;
        }
        #pragma unroll
        for (int o = 16; o; o >>= 1) {
            last = max(last, __shfl_down_sync(0xffffffffu, last, o));
            anyp |= __shfl_down_sync(0xffffffffu, anyp, o);
        }
        if (lane == 0) { s_last[warp] = last; s_any[warp] = anyp; }
        __syncthreads();
        if (tid == 0) {
            int L = -1, A = 0;
            #pragma unroll
            for (int i = 0; i < 8; i++) { L = max(L, s_last[i]); A |= s_any[i]; }
            int rlp = L < 0 ? 0 : L;
            int vlp = (rlp > 0 && rlp < MAXRL - 1) ? rlp + 1 : rlp;
            g_vlp[b] = vlp;
            sh_pos = QQ + rlp;
            s_any[0] = !A;                     // penalty flag (reuse smem)
            out[OFF_VLP + b] = (float)vlp;
            out[OFF_RLP + b] = (float)rlp;
        }
        __syncthreads();
        int pen = s_any[0];

        // score dot at gathered row
        const float4* h  = (const float4*)(hidden + ((size_t)b * LL + sh_pos) * DD);
        const float4* w4 = (const float4*)wb;
        float acc = 0.f;
        #pragma unroll
        for (int i = tid; i < DD / 4; i += 256) {
            float4 v = h[i]; float4 w = w4[i];
            acc += v.x * w.x + v.y * w.y + v.z * w.z + v.w * w.w;
        }
        #pragma unroll
        for (int o = 16; o; o >>= 1) acc += __shfl_down_sync(0xffffffffu, acc, o);
        if (lane == 0) red[warp] = acc;
        __syncthreads();
        if (tid == 0) {
            float s = 0.f;
            #pragma unroll
            for (int i = 0; i < 8; i++) s += red[i];
            if (pen) s = -3.0f;                // REWARD_PENALTY
            g_score[b] = s;
            out[OFF_SC + b] = s;
        }

        // kl / kl_rewards (overlaps the DRAM stream of value blocks)
        int base = b * RR;
        #pragma unroll
        for (int k = 0; k < 4; k++) {
            int idx = base + k * 256 + tid;
            float kl  = gen[idx] - ref[idx];
            out[OFF_KL  + idx] = kl;
            out[OFF_KLR + idx] = -0.1f * kl;   // KL_COEFF
        }
    }
}

// ========================================================================
// K_B: GAE + whitening. 32 blocks x 1024 THREADS (one batch per block,
// one element per thread -> max MLP on the latency-bound memory phases).
// All inputs L2-hot (written by K_A). Scan runs on warp 0 via stride-33
// SMEM transpose. 32-arrival monotonic-epoch grid barrier for stats.
// ========================================================================
__global__ void __launch_bounds__(1024) k_gae_whiten(
    const int* __restrict__ pad, float* __restrict__ out)
{
    __shared__ float svm[32 * 33];    // vm: element t at (t>>5)*33 + (t&31)
    __shared__ float su [32 * 33];    // u-partials, then reused for adv
    __shared__ double s_red[3][32];
    __shared__ double sh_mean, sh_inv;

    const float c = GAMMA_F * LMBDA_F;     // 0.9405
    int t = threadIdx.x;                   // 0..1023 = timestep
    int lane = t & 31, warp = t >> 5;
    int b = blockIdx.x;
    int base = b * RR;
    int idx = base + t;
    int vlp = g_vlp[b];
    float score = g_score[b];
    int pp = warp * 33 + lane;

    // ---- pass 1: 1 elem/thread, all L2-hot ----
    float vm  = out[OFF_VAL + idx];        // final masked value from K_A
    float klr = out[OFF_KLR + idx];
    int   pd  = pad[idx];
    float r = klr + ((t == vlp) ? score : 0.f);
    svm[pp] = vm;
    su [pp] = r - vm;                      // gamma*v_next added in pass 2
    __syncthreads();

    // ---- pass 2: suffix scan on warp 0 only ----
    if (warp == 0) {
        float u[32];
        #pragma unroll
        for (int j = 0; j < 32; j++) {
            int qq = lane * 33 + j;
            float vnext = (j < 31) ? svm[qq + 1]
                        : (lane < 31 ? svm[(lane + 1) * 33] : 0.f);  // v[1024]=0
            u[j] = su[qq] + GAMMA_F * vnext;
        }
        #pragma unroll
        for (int j = 30; j >= 0; j--) u[j] += c * u[j + 1];   // intra-lane scan

        float x = u[0];
        float W = c;
        W = W * W; W = W * W; W = W * W; W = W * W; W = W * W;   // c^32
        #pragma unroll
        for (int o = 1; o < 32; o <<= 1) {
            float oth = __shfl_down_sync(0xffffffffu, x, o);
            x += W * ((lane + o < 32) ? oth : 0.f);
            W *= W;
        }
        float carry = __shfl_down_sync(0xffffffffu, x, 1);
        if (lane == 31) carry = 0.f;

        float pw = c;
        #pragma unroll
        for (int j = 31; j >= 0; j--) {
            su[lane * 33 + j] = u[j] + pw * carry;   // adv
            pw *= c;
        }
    }
    __syncthreads();

    // ---- pass 3: returns + masked double partials (deterministic) ----
    float adv = su[pp];
    out[OFF_RET + idx] = adv + vm;

    double da = 0.0, dq = 0.0, dn = 0.0;
    if (pd == 0) {
        da = (double)adv;
        dq = (double)adv * (double)adv;
        dn = 1.0;
    }
    #pragma unroll
    for (int o = 16; o; o >>= 1) {
        da += __shfl_down_sync(0xffffffffu, da, o);
        dq += __shfl_down_sync(0xffffffffu, dq, o);
        dn += __shfl_down_sync(0xffffffffu, dn, o);
    }
    if (lane == 0) { s_red[0][warp] = da; s_red[1][warp] = dq; s_red[2][warp] = dn; }
    __syncthreads();
    if (warp == 0) {
        double ra = s_red[0][lane], rq = s_red[1][lane], rn = s_red[2][lane];
        #pragma unroll
        for (int o = 16; o; o >>= 1) {
            ra += __shfl_down_sync(0xffffffffu, ra, o);
            rq += __shfl_down_sync(0xffffffffu, rq, o);
            rn += __shfl_down_sync(0xffffffffu, rn, o);
        }
        if (lane == 0) {
            g_psum[b] = ra; g_psq[b] = rq; g_pcnt[b] = rn;
            __threadfence();               // partials visible before arrive
        }
    }
    __syncthreads();

    // ---- 32-arrival grid barrier (monotonic epoch, replay-safe) ----
    if (threadIdx.x == 0) {
        unsigned my = atomicAdd(&g_stats, 1u);
        unsigned target = ((my >> 5) + 1u) << 5;     // next multiple of 32
        while (*(volatile unsigned*)&g_stats < target) { }
    }
    __syncthreads();
    __threadfence();                       // acquire partials

    // ---- pass 4: redundant stats (warp 0) + whiten ----
    if (threadIdx.x < 32) {
        double ra = *(volatile double*)&g_psum[lane];
        double rq = *(volatile double*)&g_psq [lane];
        double rn = *(volatile double*)&g_pcnt[lane];
        #pragma unroll
        for (int o = 16; o; o >>= 1) {
            ra += __shfl_down_sync(0xffffffffu, ra, o);
            rq += __shfl_down_sync(0xffffffffu, rq, o);
            rn += __shfl_down_sync(0xffffffffu, rn, o);
        }
        if (lane == 0) {
            double mean = ra / rn;
            double var  = (rq / rn - mean * mean) * (rn / (rn - 1.0));
            sh_mean = mean;
            sh_inv  = 1.0 / sqrt(var + 1e-8);
        }
    }
    __syncthreads();
    float w = (float)(((double)adv - sh_mean) * sh_inv);
    out[OFF_ADV + idx] = (pd == 0) ? w : 0.f;
}

// ========================================================================
extern "C" void kernel_launch(void* const* d_in, const int* in_sizes, int n_in,
                              void* d_out, int out_size) {
    const float* hidden = (const float*)d_in[0];
    const float* wb     = (const float*)d_in[1];
    const float* wa     = (const float*)d_in[2];
    const float* gen    = (const float*)d_in[3];
    const float* ref    = (const float*)d_in[4];
    const int*   pad    = (const int*)d_in[5];   // JAX bool -> int32 marshalling
    float* out = (float*)d_out;

    k_main      <<<NVB + BB, 256>>>(hidden, wb, wa, pad, gen, ref, out);
    k_gae_whiten<<<BB,      1024>>>(pad, out);
}

// round 17
// speedup vs baseline: 1.3300x; 1.0883x over previous
#include <cuda_runtime.h>
#include <cstdint>

// Problem constants (match reference)
#define BB 32
#define QQ 512
#define RR 1024
#define LL 1536
#define DD 2048
#define MAXRL 1024
#define GAMMA_F 0.99f
#define LMBDA_F 0.95f

#define NVB (BB*RR/8)          // 4096 value blocks

// ---------------- output layout (flattened tuple, float32) ----------------
#define OFF_VAL 0
#define OFF_VPM (BB*RR)
#define OFF_VLP (2*BB*RR)
#define OFF_SC  (2*BB*RR + BB)
#define OFF_RLP (2*BB*RR + 2*BB)
#define OFF_KL  (2*BB*RR + 3*BB)
#define OFF_KLR (3*BB*RR + 3*BB)
#define OFF_ADV (4*BB*RR + 3*BB)
#define OFF_RET (5*BB*RR + 3*BB)

// ---------------- device scratch (no allocations allowed) ----------------
__device__ double   g_psum[BB];
__device__ double   g_psq[BB];
__device__ double   g_pcnt[BB];
__device__ unsigned g_stats;   // monotonic epoch counter (+32 per launch,
                               // zero at module load, replay-safe, no reset)

// ========================================================================
// K_A: LEAN pure-roofline kernel. 4096 blocks x 256 threads, warp-per-row
// (8 rows/block), float4 loads, weights staged in SMEM. Writes RAW dot
// products only (masking happens in K_B). Triggers PDL completion.
// ========================================================================
__global__ void __launch_bounds__(256) k_values(
    const float* __restrict__ hidden, const float* __restrict__ wb,
    const float* __restrict__ wa, float* __restrict__ out)
{
    __shared__ float ws[DD];
    int tid = threadIdx.x;
    #pragma unroll
    for (int i = tid; i < DD; i += 256) ws[i] = wb[i] + wa[i];
    __syncthreads();

    int warp = tid >> 5, lane = tid & 31;
    int row = blockIdx.x * 8 + warp;          // 0 .. 32767
    int b = row >> 10, t = row & 1023;
    const float4* h  = (const float4*)(hidden + ((size_t)b * LL + (QQ - 1) + t) * DD);
    const float4* w4 = (const float4*)ws;

    float acc = 0.f;
    #pragma unroll
    for (int k = 0; k < 16; k++) {
        int i4 = lane + k * 32;
        float4 v = h[i4];
        float4 w = w4[i4];
        acc += v.x * w.x + v.y * w.y + v.z * w.z + v.w * w.w;
    }
    #pragma unroll
    for (int o = 16; o; o >>= 1) acc += __shfl_down_sync(0xffffffffu, acc, o);
    if (lane == 0) out[OFF_VAL + row] = acc;   // raw, unmasked

#if __CUDA_ARCH__ >= 900
    cudaTriggerProgrammaticLaunchCompletion();
#endif
}

// ========================================================================
// K_B: everything else, launched with programmatic stream serialization so
// its PRE-SYNC phase overlaps K_A. One block per batch, 32 x 256.
//  pre-sync  (independent of K_A): meta (rlp/vlp/penalty), score dot,
//            kl / kl_rewards.
//  cudaGridDependencySynchronize()
//  post-sync (depends on raw values): mask fixup -> values/vpm, stride-33
//            SMEM stage, warp-0 suffix scan, returns, masked double
//            partials, 32-arrival epoch barrier, whitening.
// ========================================================================
__global__ void __launch_bounds__(256) k_rest(
    const float* __restrict__ hidden, const float* __restrict__ wb,
    const int* __restrict__ pad, const float* __restrict__ gen,
    const float* __restrict__ ref, float* __restrict__ out)
{
    __shared__ int s_last[8], s_any[8];
    __shared__ int sh_pos, sh_vlp;
    __shared__ float red[8];
    __shared__ float sh_score;
    __shared__ float svm[32 * 33];    // vm: element t at (t>>5)*33 + (t&31)
    __shared__ float su [32 * 33];    // u-partials, then reused for adv
    __shared__ double s_red[3][8];
    __shared__ double sh_mean, sh_inv;

    const float c = GAMMA_F * LMBDA_F;     // 0.9405
    int tid = threadIdx.x;
    int lane = tid & 31, warp = tid >> 5;
    int b = blockIdx.x;
    int base = b * RR;

    // ================= PRE-SYNC (overlaps K_A) =================
    // meta: rlp / vlp / penalty from int32-marshalled bool mask
    const int* p = pad + (size_t)b * RR;
    int last = -1, anyp = 0;
    #pragma unroll
    for (int k = 0; k < 4; k++) {
        int i = k * 256 + tid;
        int v = p[i];
        anyp |= v;
        if (!v) last = i;              // i increasing -> max survives
    }
    #pragma unroll
    for (int o = 16; o; o >>= 1) {
        last = max(last, __shfl_down_sync(0xffffffffu, last, o));
        anyp |= __shfl_down_sync(0xffffffffu, anyp, o);
    }
    if (lane == 0) { s_last[warp] = last; s_any[warp] = anyp; }
    __syncthreads();
    if (tid == 0) {
        int L = -1, A = 0;
        #pragma unroll
        for (int i = 0; i < 8; i++) { L = max(L, s_last[i]); A |= s_any[i]; }
        int rlp = L < 0 ? 0 : L;
        int vlp = (rlp > 0 && rlp < MAXRL - 1) ? rlp + 1 : rlp;
        sh_vlp = vlp;
        sh_pos = QQ + rlp;
        s_any[0] = !A;                 // penalty flag (reuse smem)
        out[OFF_VLP + b] = (float)vlp;
        out[OFF_RLP + b] = (float)rlp;
    }
    __syncthreads();
    int pen = s_any[0];

    // score dot at gathered row (hidden is an input: independent of K_A)
    {
        const float4* h  = (const float4*)(hidden + ((size_t)b * LL + sh_pos) * DD);
        const float4* w4 = (const float4*)wb;
        float acc = 0.f;
        #pragma unroll
        for (int i = tid; i < DD / 4; i += 256) {
            float4 v = h[i]; float4 w = w4[i];
            acc += v.x * w.x + v.y * w.y + v.z * w.z + v.w * w.w;
        }
        #pragma unroll
        for (int o = 16; o; o >>= 1) acc += __shfl_down_sync(0xffffffffu, acc, o);
        if (lane == 0) red[warp] = acc;
        __syncthreads();
        if (tid == 0) {
            float s = 0.f;
            #pragma unroll
            for (int i = 0; i < 8; i++) s += red[i];
            if (pen) s = -3.0f;        // REWARD_PENALTY
            sh_score = s;
            out[OFF_SC + b] = s;
        }
    }

    // kl / kl_rewards
    float klrk[4];
    int   pdk[4];
    #pragma unroll
    for (int k = 0; k < 4; k++) {
        int t = k * 256 + tid;
        int idx = base + t;
        float kl  = gen[idx] - ref[idx];
        float klr = -0.1f * kl;        // KL_COEFF
        klrk[k] = klr;
        pdk[k]  = p[t];
        out[OFF_KL  + idx] = kl;
        out[OFF_KLR + idx] = klr;
    }
    __syncthreads();
    int vlp = sh_vlp;
    float score = sh_score;

    // ================= WAIT FOR K_A =================
#if __CUDA_ARCH__ >= 900
    cudaGridDependencySynchronize();
#endif

    // ================= POST-SYNC =================
    // pass 1: mask fixup, emit values/vpm, stage vm & u
    float vmk[4];
    #pragma unroll
    for (int k = 0; k < 4; k++) {
        int t = k * 256 + tid;
        int idx = base + t;
        float raw = out[OFF_VAL + idx];
        int vpm = (pdk[k] != 0) && (t != vlp);
        float vm = vpm ? 0.f : raw;
        vmk[k] = vm;
        out[OFF_VAL + idx] = vm;
        out[OFF_VPM + idx] = vpm ? 1.f : 0.f;
        float r = klrk[k] + ((t == vlp) ? score : 0.f);
        int pp = (t >> 5) * 33 + (t & 31);
        svm[pp] = vm;
        su [pp] = r - vm;              // gamma*v_next added in pass 2
    }
    __syncthreads();

    // pass 2: suffix scan on warp 0
    if (warp == 0) {
        float u[32];
        #pragma unroll
        for (int j = 0; j < 32; j++) {
            int pp = lane * 33 + j;
            float vnext = (j < 31) ? svm[pp + 1]
                        : (lane < 31 ? svm[(lane + 1) * 33] : 0.f);  // v[1024]=0
            u[j] = su[pp] + GAMMA_F * vnext;
        }
        #pragma unroll
        for (int j = 30; j >= 0; j--) u[j] += c * u[j + 1];   // intra-lane scan

        float x = u[0];
        float W = c;
        W = W * W; W = W * W; W = W * W; W = W * W; W = W * W;   // c^32
        #pragma unroll
        for (int o = 1; o < 32; o <<= 1) {
            float oth = __shfl_down_sync(0xffffffffu, x, o);
            x += W * ((lane + o < 32) ? oth : 0.f);
            W *= W;
        }
        float carry = __shfl_down_sync(0xffffffffu, x, 1);
        if (lane == 31) carry = 0.f;

        float pw = c;
        #pragma unroll
        for (int j = 31; j >= 0; j--) {
            su[lane * 33 + j] = u[j] + pw * carry;   // adv
            pw *= c;
        }
    }
    __syncthreads();

    // pass 3: returns + masked double partials
    double da = 0.0, dq = 0.0, dn = 0.0;
    float advk[4];
    #pragma unroll
    for (int k = 0; k < 4; k++) {
        int t = k * 256 + tid;
        int idx = base + t;
        float adv = su[(t >> 5) * 33 + (t & 31)];
        advk[k] = adv;
        out[OFF_RET + idx] = adv + vmk[k];
        if (pdk[k] == 0) {
            da += (double)adv;
            dq += (double)adv * (double)adv;
            dn += 1.0;
        }
    }
    #pragma unroll
    for (int o = 16; o; o >>= 1) {
        da += __shfl_down_sync(0xffffffffu, da, o);
        dq += __shfl_down_sync(0xffffffffu, dq, o);
        dn += __shfl_down_sync(0xffffffffu, dn, o);
    }
    if (lane == 0) { s_red[0][warp] = da; s_red[1][warp] = dq; s_red[2][warp] = dn; }
    __syncthreads();
    if (tid == 0) {
        double S = 0, Q2 = 0, N = 0;
        #pragma unroll
        for (int i = 0; i < 8; i++) { S += s_red[0][i]; Q2 += s_red[1][i]; N += s_red[2][i]; }
        g_psum[b] = S; g_psq[b] = Q2; g_pcnt[b] = N;
        __threadfence();               // partials visible before arrive
    }
    __syncthreads();

    // 32-arrival grid barrier (monotonic epoch, replay-safe)
    if (tid == 0) {
        unsigned my = atomicAdd(&g_stats, 1u);
        unsigned target = ((my >> 5) + 1u) << 5;     // next multiple of 32
        while (*(volatile unsigned*)&g_stats < target) { }
    }
    __syncthreads();
    __threadfence();                   // acquire partials

    // pass 4: redundant stats (warp 0) + whiten
    if (tid < 32) {
        double ra = *(volatile double*)&g_psum[lane];
        double rq = *(volatile double*)&g_psq [lane];
        double rn = *(volatile double*)&g_pcnt[lane];
        #pragma unroll
        for (int o = 16; o; o >>= 1) {
            ra += __shfl_down_sync(0xffffffffu, ra, o);
            rq += __shfl_down_sync(0xffffffffu, rq, o);
            rn += __shfl_down_sync(0xffffffffu, rn, o);
        }
        if (lane == 0) {
            double mean = ra / rn;
            double var  = (rq / rn - mean * mean) * (rn / (rn - 1.0));
            sh_mean = mean;
            sh_inv  = 1.0 / sqrt(var + 1e-8);
        }
    }
    __syncthreads();
    double mean = sh_mean, inv = sh_inv;
    #pragma unroll
    for (int k = 0; k < 4; k++) {
        int idx = base + k * 256 + tid;
        float w = (float)(((double)advk[k] - mean) * inv);
        out[OFF_ADV + idx] = (pdk[k] == 0) ? w : 0.f;
    }
}

// ========================================================================
extern "C" void kernel_launch(void* const* d_in, const int* in_sizes, int n_in,
                              void* d_out, int out_size) {
    const float* hidden = (const float*)d_in[0];
    const float* wb     = (const float*)d_in[1];
    const float* wa     = (const float*)d_in[2];
    const float* gen    = (const float*)d_in[3];
    const float* ref    = (const float*)d_in[4];
    const int*   pad    = (const int*)d_in[5];   // JAX bool -> int32 marshalling
    float* out = (float*)d_out;

    k_values<<<NVB, 256>>>(hidden, wb, wa, out);

    // PDL: K_B launches concurrently; its pre-sync phase overlaps K_A, and
    // cudaGridDependencySynchronize() gates the dependent post-sync phase.
    cudaLaunchAttribute attrs[1];
    attrs[0].id = cudaLaunchAttributeProgrammaticStreamSerialization;
    attrs[0].val.programmaticStreamSerializationAllowed = 1;
    cudaLaunchConfig_t cfg = {};
    cfg.gridDim  = dim3(BB, 1, 1);
    cfg.blockDim = dim3(256, 1, 1);
    cfg.dynamicSmemBytes = 0;
    cfg.stream = 0;
    cfg.attrs = attrs;
    cfg.numAttrs = 1;
    cudaLaunchKernelEx(&cfg, k_rest, hidden, wb, pad, gen, ref, out);
}